// round 2
// baseline (speedup 1.0000x reference)
#include <cuda_runtime.h>
#include <cuda_bf16.h>

#define BATCH 16384
#define KS 20
#define DIM 256
#define NH 4
#define EPSF 1e-8f

// ---------------- scratch (device globals; allocations are forbidden) ------
__device__ float g_ctx2[(long)BATCH * 2 * DIM];   // [x | hmean] for imp MLP
__device__ float g_had [(long)BATCH * 128];       // ad-MLP hidden
__device__ float g_himp[(long)BATCH * DIM];       // imp-MLP hidden
__device__ float g_q   [(long)BATCH * DIM];       // q projection
__device__ float g_qk  [(long)BATCH * NH * DIM];  // Wk_h^T q_h per head
__device__ float g_s   [(long)BATCH * NH * DIM];  // attn-weighted sums of st
__device__ float g_ctx [(long)BATCH * DIM];       // attention context
__device__ float g_stat[BATCH];
__device__ float g_anom[BATCH];

__device__ __forceinline__ float* bufsel(int s) {
    switch (s) {
        case 1: return g_ctx2; case 2: return g_had;  case 3: return g_himp;
        case 4: return g_q;    case 5: return g_qk;   case 6: return g_s;
        case 7: return g_ctx;
    }
    return nullptr;
}

__device__ __forceinline__ float warp_sum(float v) {
    #pragma unroll
    for (int o = 16; o; o >>= 1) v += __shfl_down_sync(0xffffffffu, v, o);
    return v;
}

__device__ __forceinline__ unsigned long long fma2(unsigned long long a,
                                                   unsigned long long b,
                                                   unsigned long long c) {
    unsigned long long d;
    asm("fma.rn.f32x2 %0, %1, %2, %3;" : "=l"(d) : "l"(a), "l"(b), "l"(c));
    return d;
}
__device__ __forceinline__ float2 u2f(unsigned long long v) {
    float2 f;
    f.x = __uint_as_float((unsigned)v);
    f.y = __uint_as_float((unsigned)(v >> 32));
    return f;
}

// ---------------- K1: masked stats + stat anomaly + st rows 1..19 ----------
__global__ __launch_bounds__(256) void k1_stats(
    const float* __restrict__ storage, const float* __restrict__ xmsg,
    float* __restrict__ out_st)
{
    __shared__ float sm[KS][DIM];
    __shared__ float smask[KS];
    __shared__ float sred[8];

    int b = blockIdx.x, tid = threadIdx.x;
    const float* row = storage + (long)b * KS * DIM;
    #pragma unroll
    for (int j = 0; j < KS; j++) sm[j][tid] = row[j * DIM + tid];
    __syncthreads();

    int w = tid >> 5, lane = tid & 31;
    for (int j = w; j < KS; j += 8) {
        float s = 0.f;
        #pragma unroll
        for (int i = lane; i < DIM; i += 32) s += fabsf(sm[j][i]);
        s = warp_sum(s);
        if (lane == 0) smask[j] = (s > 0.f) ? 1.f : 0.f;
    }
    __syncthreads();

    float denom = EPSF;
    #pragma unroll
    for (int j = 0; j < KS; j++) denom += smask[j];

    int d = tid;
    float m = 0.f;
    #pragma unroll
    for (int j = 0; j < KS; j++) m += sm[j][d] * smask[j];
    float hmean = m / denom;
    float v = 0.f;
    #pragma unroll
    for (int j = 0; j < KS; j++) {
        float df = sm[j][d] - hmean;
        v += df * df * smask[j];
    }
    float hstd = sqrtf(v / denom);

    float xd = xmsg[(long)b * DIM + d];
    float z = fabsf((xd - hmean) / (hstd + EPSF));
    float c = (z > 2.0f) ? 1.f : 0.f;
    c = warp_sum(c);
    if (lane == 0) sred[w] = c;
    __syncthreads();
    if (tid == 0) {
        float t = 0.f;
        #pragma unroll
        for (int i = 0; i < 8; i++) t += sred[i];
        g_stat[b] = t / (float)DIM;
    }

    g_ctx2[(long)b * 512 + d]       = xd;
    g_ctx2[(long)b * 512 + 256 + d] = hmean;

    // st[j] = storage[j-1] * 0.95^(j-1), j = 1..19 (decay then roll)
    float dec = 1.f;
    float* orow = out_st + (long)b * KS * DIM;
    #pragma unroll
    for (int j = 1; j < KS; j++) {
        orow[j * DIM + d] = sm[j - 1][d] * dec;
        dec *= 0.95f;
    }
}

// ---------------- K2: learned anomaly + combine ----------------------------
__global__ __launch_bounds__(256) void k2_anom(
    const float* __restrict__ ad_w2, const float* __restrict__ ad_b2)
{
    int w = threadIdx.x >> 5, lane = threadIdx.x & 31;
    int row = blockIdx.x * 8 + w;
    const float* h = g_had + (long)row * 128;
    float s = 0.f;
    #pragma unroll
    for (int i = lane; i < 128; i += 32) s += h[i] * ad_w2[i];
    s = warp_sum(s);
    if (lane == 0) {
        float t = s + ad_b2[0];
        float learned = 1.f / (1.f + expf(-t));
        g_anom[row] = 0.5f * g_stat[row] + 0.5f * learned;
    }
}

// ---------------- K4: importance + st row 0 --------------------------------
__global__ __launch_bounds__(256) void k4_imp(
    const float* __restrict__ imp_w2, const float* __restrict__ imp_b2,
    const float* __restrict__ xmsg, float* __restrict__ out_st)
{
    __shared__ float sred[8];
    __shared__ float simp;
    int b = blockIdx.x, d = threadIdx.x;
    int w = d >> 5, lane = d & 31;
    float p = g_himp[(long)b * DIM + d] * imp_w2[d];
    p = warp_sum(p);
    if (lane == 0) sred[w] = p;
    __syncthreads();
    if (d == 0) {
        float t = imp_b2[0];
        #pragma unroll
        for (int i = 0; i < 8; i++) t += sred[i];
        float sp = fmaxf(t, 0.f) + log1pf(expf(-fabsf(t)));   // softplus
        simp = sp * (1.f + g_anom[b]);
    }
    __syncthreads();
    out_st[(long)b * KS * DIM + d] = xmsg[(long)b * DIM + d] * simp;
}

// ---------------- K7: scores -> softmax -> weighted sums -------------------
__global__ __launch_bounds__(256) void k7_attn(const float* __restrict__ out_st)
{
    __shared__ float st_s[KS][DIM];
    __shared__ float qk_s[NH][DIM];
    __shared__ float sc[NH][KS];

    int b = blockIdx.x, tid = threadIdx.x;
    const float* srow = out_st + (long)b * KS * DIM;
    #pragma unroll
    for (int j = 0; j < KS; j++) st_s[j][tid] = srow[j * DIM + tid];
    #pragma unroll
    for (int h = 0; h < NH; h++)
        qk_s[h][tid] = g_qk[(long)b * NH * DIM + h * DIM + tid];
    __syncthreads();

    int w = tid >> 5, lane = tid & 31;
    for (int id = w; id < NH * KS; id += 8) {
        int h = id / KS, j = id % KS;
        float s = 0.f;
        #pragma unroll
        for (int i = lane; i < DIM; i += 32) s += qk_s[h][i] * st_s[j][i];
        s = warp_sum(s);
        if (lane == 0) sc[h][j] = s * 0.125f;   // 1/sqrt(64)
    }
    __syncthreads();

    if (tid < NH) {
        float mx = -1e30f;
        #pragma unroll
        for (int j = 0; j < KS; j++) mx = fmaxf(mx, sc[tid][j]);
        float su = 0.f;
        #pragma unroll
        for (int j = 0; j < KS; j++) {
            float e = expf(sc[tid][j] - mx);
            sc[tid][j] = e; su += e;
        }
        float inv = 1.f / su;
        #pragma unroll
        for (int j = 0; j < KS; j++) sc[tid][j] *= inv;
    }
    __syncthreads();

    int d = tid;
    #pragma unroll
    for (int h = 0; h < NH; h++) {
        float a = 0.f;
        #pragma unroll
        for (int j = 0; j < KS; j++) a += sc[h][j] * st_s[j][d];
        g_s[(long)b * NH * DIM + h * DIM + d] = a;
    }
}

// ---------------- generic fp32 GEMM, 128x64 tile, f32x2 FMA ----------------
// C[m, cZ*z + n0+n] = act( sum_k A[m*lda + aZ*z + k] * B(k, n) + bias )
// B normal (bTrans=0): B[(n0+n)*ldb + bZ*z + k]     (weights, [n][k])
// B trans  (bTrans=1): B[k*ldb + bZ*z + n0+n]       ([k][n])
__global__ __launch_bounds__(256) void gemm128x64(
    const float* __restrict__ Aext, int aSel, int lda, int aZ,
    const float* __restrict__ Bw, int bTrans, int ldb, long bZ,
    const float* __restrict__ bias, int biasZ,
    float* __restrict__ Cext, int cSel, int ldc, int cZ,
    int Ktot, int act)
{
    __shared__ float As[16][132];
    __shared__ float Bs[16][68];

    const float* A = aSel ? (const float*)bufsel(aSel) : Aext;
    float* C = cSel ? bufsel(cSel) : Cext;

    int z = blockIdx.z;
    int m0 = blockIdx.x * 128;
    int n0 = blockIdx.y * 64;
    const float* Ab = A + (long)aZ * z;
    const float* Bb = Bw + bZ * z;

    int tid = threadIdx.x;
    int tm = (tid >> 4) * 8;      // 0..120
    int tn = (tid & 15) * 4;      // 0..60

    unsigned long long acc[8][2];
    #pragma unroll
    for (int i = 0; i < 8; i++) { acc[i][0] = 0ull; acc[i][1] = 0ull; }

    int arow = tid >> 2;
    int akq  = (tid & 3) * 4;

    for (int c0 = 0; c0 < Ktot; c0 += 16) {
        #pragma unroll
        for (int r = 0; r < 2; r++) {
            int row = arow + r * 64;
            float4 v = *(const float4*)(Ab + (long)(m0 + row) * lda + c0 + akq);
            As[akq + 0][row] = v.x; As[akq + 1][row] = v.y;
            As[akq + 2][row] = v.z; As[akq + 3][row] = v.w;
        }
        if (bTrans) {
            int krow = tid >> 4;
            int nq   = (tid & 15) * 4;
            float4 v = *(const float4*)(Bb + (long)(c0 + krow) * ldb + n0 + nq);
            *(float4*)&Bs[krow][nq] = v;
        } else {
            int nrow = tid >> 2;
            int kq   = (tid & 3) * 4;
            float4 v = *(const float4*)(Bb + (long)(n0 + nrow) * ldb + c0 + kq);
            Bs[kq + 0][nrow] = v.x; Bs[kq + 1][nrow] = v.y;
            Bs[kq + 2][nrow] = v.z; Bs[kq + 3][nrow] = v.w;
        }
        __syncthreads();

        #pragma unroll
        for (int kk = 0; kk < 16; kk++) {
            float4 b4 = *(const float4*)&Bs[kk][tn];
            unsigned long long b01, b23;
            asm("mov.b64 %0,{%1,%2};" : "=l"(b01)
                : "r"(__float_as_uint(b4.x)), "r"(__float_as_uint(b4.y)));
            asm("mov.b64 %0,{%1,%2};" : "=l"(b23)
                : "r"(__float_as_uint(b4.z)), "r"(__float_as_uint(b4.w)));
            float4 a0 = *(const float4*)&As[kk][tm];
            float4 a1 = *(const float4*)&As[kk][tm + 4];
            float av[8] = {a0.x, a0.y, a0.z, a0.w, a1.x, a1.y, a1.z, a1.w};
            #pragma unroll
            for (int i = 0; i < 8; i++) {
                unsigned long long a2;
                asm("mov.b64 %0,{%1,%1};" : "=l"(a2) : "r"(__float_as_uint(av[i])));
                acc[i][0] = fma2(a2, b01, acc[i][0]);
                acc[i][1] = fma2(a2, b23, acc[i][1]);
            }
        }
        __syncthreads();
    }

    float bv[4] = {0.f, 0.f, 0.f, 0.f};
    if (bias) {
        #pragma unroll
        for (int j = 0; j < 4; j++) bv[j] = bias[biasZ * z + n0 + tn + j];
    }
    #pragma unroll
    for (int i = 0; i < 8; i++) {
        float2 c01 = u2f(acc[i][0]);
        float2 c23 = u2f(acc[i][1]);
        float4 r;
        r.x = c01.x + bv[0]; r.y = c01.y + bv[1];
        r.z = c23.x + bv[2]; r.w = c23.y + bv[3];
        if (act == 1) {
            r.x = fmaxf(r.x, 0.f); r.y = fmaxf(r.y, 0.f);
            r.z = fmaxf(r.z, 0.f); r.w = fmaxf(r.w, 0.f);
        }
        *(float4*)(C + (long)(m0 + tm + i) * ldc + (long)cZ * z + n0 + tn) = r;
    }
}

// ---------------------------------------------------------------------------
extern "C" void kernel_launch(void* const* d_in, const int* in_sizes, int n_in,
                              void* d_out, int out_size) {
    const float* storage = (const float*)d_in[0];
    const float* x       = (const float*)d_in[1];
    const float* ad_w1   = (const float*)d_in[2];
    const float* ad_b1   = (const float*)d_in[3];
    const float* ad_w2   = (const float*)d_in[4];
    const float* ad_b2   = (const float*)d_in[5];
    const float* imp_w1  = (const float*)d_in[6];
    const float* imp_b1  = (const float*)d_in[7];
    const float* imp_w2  = (const float*)d_in[8];
    const float* imp_b2  = (const float*)d_in[9];
    const float* w_in    = (const float*)d_in[10];
    const float* b_in    = (const float*)d_in[11];
    const float* w_out   = (const float*)d_in[12];
    const float* b_out   = (const float*)d_in[13];

    float* st  = (float*)d_out;                       // [B,K,D]
    float* agg = st + (long)BATCH * KS * DIM;         // [B,D]

    // stats, mask, hmean/hstd, stat anomaly, st rows 1..19, ctx2
    k1_stats<<<BATCH, 256>>>(storage, x, st);
    // ad-MLP hidden: relu(x @ ad_w1^T + ad_b1) -> g_had [B,128]
    gemm128x64<<<dim3(128, 2, 1), 256>>>(x, 0, 256, 0, ad_w1, 0, 256, 0,
                                         ad_b1, 0, nullptr, 2, 128, 0, 256, 1);
    // learned anomaly + combine -> g_anom
    k2_anom<<<BATCH / 8, 256>>>(ad_w2, ad_b2);
    // imp-MLP hidden: relu(ctx2 @ imp_w1^T + imp_b1) -> g_himp [B,256]
    gemm128x64<<<dim3(128, 4, 1), 256>>>(nullptr, 1, 512, 0, imp_w1, 0, 512, 0,
                                         imp_b1, 0, nullptr, 3, 256, 0, 512, 1);
    // importance scalar + st row 0
    k4_imp<<<BATCH, 256>>>(imp_w2, imp_b2, x, st);
    // q = x @ wq^T + bq -> g_q [B,256]
    gemm128x64<<<dim3(128, 4, 1), 256>>>(x, 0, 256, 0, w_in, 0, 256, 0,
                                         b_in, 0, nullptr, 4, 256, 0, 256, 0);
    // qk[b,h,:] = Wk_h^T q_h  (z = head, K=64, B operand [k][n]) -> g_qk
    gemm128x64<<<dim3(128, 4, 4), 256>>>(nullptr, 4, 256, 64,
                                         w_in + 256 * 256, 1, 256, 64L * 256,
                                         nullptr, 0, nullptr, 5, 1024, 256, 64, 0);
    // scores -> softmax -> weighted st sums -> g_s [B,4,256]
    k7_attn<<<BATCH, 256>>>(st);
    // ctx[b, h*64+n] = wv_h[n,:] . s[b,h,:] + bv  -> g_ctx [B,256]
    gemm128x64<<<dim3(128, 1, 4), 256>>>(nullptr, 6, 1024, 256,
                                         w_in + 512 * 256, 0, 256, 64L * 256,
                                         b_in + 512, 64, nullptr, 7, 256, 64, 256, 0);
    // agg = ctx @ attn_out_w^T + attn_out_b -> d_out tail
    gemm128x64<<<dim3(128, 4, 1), 256>>>(nullptr, 7, 256, 0, w_out, 0, 256, 0,
                                         b_out, 0, agg, 0, 256, 0, 256, 0);
    (void)in_sizes; (void)n_in; (void)out_size;
}

// round 3
// speedup vs baseline: 1.1977x; 1.1977x over previous
#include <cuda_runtime.h>
#include <cuda_bf16.h>
#include <stdint.h>

#define BATCH 16384
#define KS 20
#define DIM 256
#define NH 4
#define EPSF 1e-8f

// ---------------- scratch (device globals; allocations are forbidden) ------
__device__ float g_ctx2[(long)BATCH * 2 * DIM];   // [x | hmean] for imp MLP
__device__ float g_had [(long)BATCH * 128];       // ad-MLP hidden
__device__ float g_himp[(long)BATCH * DIM];       // imp-MLP hidden
__device__ float g_q   [(long)BATCH * DIM];       // q projection
__device__ float g_qk  [(long)BATCH * NH * DIM];  // Wk_h^T q_h per head
__device__ float g_s   [(long)BATCH * NH * DIM];  // attn-weighted sums of st
__device__ float g_ctx [(long)BATCH * DIM];       // attention context
__device__ float g_stat[BATCH];
__device__ float g_anom[BATCH];

__device__ __forceinline__ float* bufsel(int s) {
    switch (s) {
        case 1: return g_ctx2; case 2: return g_had;  case 3: return g_himp;
        case 4: return g_q;    case 5: return g_qk;   case 6: return g_s;
        case 7: return g_ctx;
    }
    return nullptr;
}

__device__ __forceinline__ float warp_sum(float v) {
    #pragma unroll
    for (int o = 16; o; o >>= 1) v += __shfl_down_sync(0xffffffffu, v, o);
    return v;
}

// ---------------- K1: masked stats + stat anomaly + st rows 1..19 ----------
__global__ __launch_bounds__(256) void k1_stats(
    const float* __restrict__ storage, const float* __restrict__ xmsg,
    float* __restrict__ out_st)
{
    __shared__ float sm[KS][DIM];
    __shared__ float smask[KS];
    __shared__ float sred[8];

    int b = blockIdx.x, tid = threadIdx.x;
    const float* row = storage + (long)b * KS * DIM;
    #pragma unroll
    for (int j = 0; j < KS; j++) sm[j][tid] = row[j * DIM + tid];
    __syncthreads();

    int w = tid >> 5, lane = tid & 31;
    for (int j = w; j < KS; j += 8) {
        float s = 0.f;
        #pragma unroll
        for (int i = lane; i < DIM; i += 32) s += fabsf(sm[j][i]);
        s = warp_sum(s);
        if (lane == 0) smask[j] = (s > 0.f) ? 1.f : 0.f;
    }
    __syncthreads();

    float denom = EPSF;
    #pragma unroll
    for (int j = 0; j < KS; j++) denom += smask[j];

    int d = tid;
    float m = 0.f;
    #pragma unroll
    for (int j = 0; j < KS; j++) m += sm[j][d] * smask[j];
    float hmean = m / denom;
    float v = 0.f;
    #pragma unroll
    for (int j = 0; j < KS; j++) {
        float df = sm[j][d] - hmean;
        v += df * df * smask[j];
    }
    float hstd = sqrtf(v / denom);

    float xd = xmsg[(long)b * DIM + d];
    float z = fabsf((xd - hmean) / (hstd + EPSF));
    float c = (z > 2.0f) ? 1.f : 0.f;
    c = warp_sum(c);
    if (lane == 0) sred[w] = c;
    __syncthreads();
    if (tid == 0) {
        float t = 0.f;
        #pragma unroll
        for (int i = 0; i < 8; i++) t += sred[i];
        g_stat[b] = t / (float)DIM;
    }

    g_ctx2[(long)b * 512 + d]       = xd;
    g_ctx2[(long)b * 512 + 256 + d] = hmean;

    float dec = 1.f;
    float* orow = out_st + (long)b * KS * DIM;
    #pragma unroll
    for (int j = 1; j < KS; j++) {
        orow[j * DIM + d] = sm[j - 1][d] * dec;
        dec *= 0.95f;
    }
}

// ---------------- K2: learned anomaly + combine ----------------------------
__global__ __launch_bounds__(256) void k2_anom(
    const float* __restrict__ ad_w2, const float* __restrict__ ad_b2)
{
    int w = threadIdx.x >> 5, lane = threadIdx.x & 31;
    int row = blockIdx.x * 8 + w;
    const float* h = g_had + (long)row * 128;
    float s = 0.f;
    #pragma unroll
    for (int i = lane; i < 128; i += 32) s += h[i] * ad_w2[i];
    s = warp_sum(s);
    if (lane == 0) {
        float t = s + ad_b2[0];
        float learned = 1.f / (1.f + expf(-t));
        g_anom[row] = 0.5f * g_stat[row] + 0.5f * learned;
    }
}

// ---------------- K4: importance + st row 0 --------------------------------
__global__ __launch_bounds__(256) void k4_imp(
    const float* __restrict__ imp_w2, const float* __restrict__ imp_b2,
    const float* __restrict__ xmsg, float* __restrict__ out_st)
{
    __shared__ float sred[8];
    __shared__ float simp;
    int b = blockIdx.x, d = threadIdx.x;
    int w = d >> 5, lane = d & 31;
    float p = g_himp[(long)b * DIM + d] * imp_w2[d];
    p = warp_sum(p);
    if (lane == 0) sred[w] = p;
    __syncthreads();
    if (d == 0) {
        float t = imp_b2[0];
        #pragma unroll
        for (int i = 0; i < 8; i++) t += sred[i];
        float sp = fmaxf(t, 0.f) + log1pf(expf(-fabsf(t)));
        simp = sp * (1.f + g_anom[b]);
    }
    __syncthreads();
    out_st[(long)b * KS * DIM + d] = xmsg[(long)b * DIM + d] * simp;
}

// ---------------- K7: scores -> softmax -> weighted sums -------------------
__global__ __launch_bounds__(256) void k7_attn(const float* __restrict__ out_st)
{
    __shared__ float st_s[KS][DIM];
    __shared__ float qk_s[NH][DIM];
    __shared__ float sc[NH][KS];

    int b = blockIdx.x, tid = threadIdx.x;
    const float* srow = out_st + (long)b * KS * DIM;
    #pragma unroll
    for (int j = 0; j < KS; j++) st_s[j][tid] = srow[j * DIM + tid];
    #pragma unroll
    for (int h = 0; h < NH; h++)
        qk_s[h][tid] = g_qk[(long)b * NH * DIM + h * DIM + tid];
    __syncthreads();

    int w = tid >> 5, lane = tid & 31;
    for (int id = w; id < NH * KS; id += 8) {
        int h = id / KS, j = id % KS;
        float s = 0.f;
        #pragma unroll
        for (int i = lane; i < DIM; i += 32) s += qk_s[h][i] * st_s[j][i];
        s = warp_sum(s);
        if (lane == 0) sc[h][j] = s * 0.125f;   // 1/sqrt(64)
    }
    __syncthreads();

    if (tid < NH) {
        float mx = -1e30f;
        #pragma unroll
        for (int j = 0; j < KS; j++) mx = fmaxf(mx, sc[tid][j]);
        float su = 0.f;
        #pragma unroll
        for (int j = 0; j < KS; j++) {
            float e = expf(sc[tid][j] - mx);
            sc[tid][j] = e; su += e;
        }
        float inv = 1.f / su;
        #pragma unroll
        for (int j = 0; j < KS; j++) sc[tid][j] *= inv;
    }
    __syncthreads();

    int d = tid;
    #pragma unroll
    for (int h = 0; h < NH; h++) {
        float a = 0.f;
        #pragma unroll
        for (int j = 0; j < KS; j++) a += sc[h][j] * st_s[j][d];
        g_s[(long)b * NH * DIM + h * DIM + d] = a;
    }
}

// ---------------- bf16x3 tensor-core GEMM, 128x64 tile ---------------------
// C[m, cZ*z + n0+n] = act( sum_k A[m*lda + aZ*z + k] * B(k, n) + bias )
// B normal (bTrans=0): B[(n0+n)*ldb + bZ*z + k]
// B trans  (bTrans=1): B[k*ldb + bZ*z + n0+n]
#define PADA 136
#define PADB 72

__device__ __forceinline__ void split2(float x, float y,
                                       uint32_t& hi, uint32_t& lo) {
    __nv_bfloat16 hx = __float2bfloat16(x);
    __nv_bfloat16 hy = __float2bfloat16(y);
    float rx = x - __bfloat162float(hx);
    float ry = y - __bfloat162float(hy);
    __nv_bfloat16 lx = __float2bfloat16(rx);
    __nv_bfloat16 ly = __float2bfloat16(ry);
    hi = ((uint32_t)__bfloat16_as_ushort(hy) << 16) | __bfloat16_as_ushort(hx);
    lo = ((uint32_t)__bfloat16_as_ushort(ly) << 16) | __bfloat16_as_ushort(lx);
}

__device__ __forceinline__ void mma16816(float* c, const uint32_t* a,
                                         const uint32_t* b) {
    asm volatile(
        "mma.sync.aligned.m16n8k16.row.col.f32.bf16.bf16.f32 "
        "{%0,%1,%2,%3},{%4,%5,%6,%7},{%8,%9},{%0,%1,%2,%3};"
        : "+f"(c[0]), "+f"(c[1]), "+f"(c[2]), "+f"(c[3])
        : "r"(a[0]), "r"(a[1]), "r"(a[2]), "r"(a[3]), "r"(b[0]), "r"(b[1]));
}

__global__ __launch_bounds__(256) void gemm_tc(
    const float* __restrict__ Aext, int aSel, int lda, int aZ,
    const float* __restrict__ Bw, int bTrans, int ldb, long bZ,
    const float* __restrict__ bias, int biasZ,
    float* __restrict__ Cext, int cSel, int ldc, int cZ,
    int Ktot, int act)
{
    __shared__ uint32_t Ahs[16][PADA], Als[16][PADA];
    __shared__ uint32_t Bhs[16][PADB], Bls[16][PADB];

    const float* A = aSel ? (const float*)bufsel(aSel) : Aext;
    float* C = cSel ? bufsel(cSel) : Cext;

    int z  = blockIdx.z;
    int m0 = blockIdx.x * 128;
    int n0 = blockIdx.y * 64;
    const float* Ab = A + (long)aZ * z;
    const float* Bb = Bw + bZ * z;

    int tid = threadIdx.x;
    int warp = tid >> 5, lane = tid & 31;
    int wm = (warp >> 1) * 32, wn = (warp & 1) * 32;
    int lr = lane >> 2, lc = lane & 3;

    float acc[2][4][4];
    #pragma unroll
    for (int i = 0; i < 2; i++)
        #pragma unroll
        for (int j = 0; j < 4; j++)
            #pragma unroll
            for (int q = 0; q < 4; q++) acc[i][j][q] = 0.f;

    for (int c0 = 0; c0 < Ktot; c0 += 32) {
        // ---- A tile 128x32 -> hi/lo bf162 pairs ----
        {
            int row = tid >> 1, kk = (tid & 1) * 16;
            const float* ap = Ab + (long)(m0 + row) * lda + c0 + kk;
            float4 v0 = *(const float4*)(ap);
            float4 v1 = *(const float4*)(ap + 4);
            float4 v2 = *(const float4*)(ap + 8);
            float4 v3 = *(const float4*)(ap + 12);
            float px[8] = {v0.x, v0.z, v1.x, v1.z, v2.x, v2.z, v3.x, v3.z};
            float py[8] = {v0.y, v0.w, v1.y, v1.w, v2.y, v2.w, v3.y, v3.w};
            int kp0 = kk >> 1;
            #pragma unroll
            for (int j = 0; j < 8; j++) {
                uint32_t h, l;
                split2(px[j], py[j], h, l);
                Ahs[kp0 + j][row] = h;
                Als[kp0 + j][row] = l;
            }
        }
        // ---- B tile 64x32 ----
        if (bTrans) {
            int kp = tid >> 4, nq = (tid & 15) * 4;
            const float* be = Bb + (long)(c0 + 2 * kp) * ldb + n0 + nq;
            float4 e = *(const float4*)(be);
            float4 o = *(const float4*)(be + ldb);
            float px[4] = {e.x, e.y, e.z, e.w};
            float py[4] = {o.x, o.y, o.z, o.w};
            #pragma unroll
            for (int j = 0; j < 4; j++) {
                uint32_t h, l;
                split2(px[j], py[j], h, l);
                Bhs[kp][nq + j] = h;
                Bls[kp][nq + j] = l;
            }
        } else {
            int n = tid >> 2, kq = (tid & 3) * 8;
            const float* bp = Bb + (long)(n0 + n) * ldb + c0 + kq;
            float4 v0 = *(const float4*)(bp);
            float4 v1 = *(const float4*)(bp + 4);
            float px[4] = {v0.x, v0.z, v1.x, v1.z};
            float py[4] = {v0.y, v0.w, v1.y, v1.w};
            int kp0 = kq >> 1;
            #pragma unroll
            for (int j = 0; j < 4; j++) {
                uint32_t h, l;
                split2(px[j], py[j], h, l);
                Bhs[kp0 + j][n] = h;
                Bls[kp0 + j][n] = l;
            }
        }
        __syncthreads();

        #pragma unroll
        for (int ks = 0; ks < 2; ks++) {
            int kpb = ks * 8;
            uint32_t ah[2][4], al[2][4];
            #pragma unroll
            for (int am = 0; am < 2; am++) {
                int r = wm + am * 16 + lr;
                ah[am][0] = Ahs[kpb + lc][r];
                ah[am][1] = Ahs[kpb + lc][r + 8];
                ah[am][2] = Ahs[kpb + 4 + lc][r];
                ah[am][3] = Ahs[kpb + 4 + lc][r + 8];
                al[am][0] = Als[kpb + lc][r];
                al[am][1] = Als[kpb + lc][r + 8];
                al[am][2] = Als[kpb + 4 + lc][r];
                al[am][3] = Als[kpb + 4 + lc][r + 8];
            }
            uint32_t bh[4][2], bl[4][2];
            #pragma unroll
            for (int an = 0; an < 4; an++) {
                int n = wn + an * 8 + lr;
                bh[an][0] = Bhs[kpb + lc][n];
                bh[an][1] = Bhs[kpb + 4 + lc][n];
                bl[an][0] = Bls[kpb + lc][n];
                bl[an][1] = Bls[kpb + 4 + lc][n];
            }
            #pragma unroll
            for (int am = 0; am < 2; am++)
                #pragma unroll
                for (int an = 0; an < 4; an++) {
                    mma16816(acc[am][an], ah[am], bh[an]);
                    mma16816(acc[am][an], ah[am], bl[an]);
                    mma16816(acc[am][an], al[am], bh[an]);
                }
        }
        __syncthreads();
    }

    // ---- epilogue ----
    #pragma unroll
    for (int am = 0; am < 2; am++) {
        #pragma unroll
        for (int an = 0; an < 4; an++) {
            int row0 = m0 + wm + am * 16 + lr;
            int col  = n0 + wn + an * 8 + lc * 2;
            float b0 = 0.f, b1 = 0.f;
            if (bias) {
                b0 = bias[biasZ * z + col];
                b1 = bias[biasZ * z + col + 1];
            }
            float v0 = acc[am][an][0] + b0, v1 = acc[am][an][1] + b1;
            float v2 = acc[am][an][2] + b0, v3 = acc[am][an][3] + b1;
            if (act == 1) {
                v0 = fmaxf(v0, 0.f); v1 = fmaxf(v1, 0.f);
                v2 = fmaxf(v2, 0.f); v3 = fmaxf(v3, 0.f);
            }
            long off = (long)cZ * z + col;
            *(float2*)(C + (long)row0 * ldc + off)       = make_float2(v0, v1);
            *(float2*)(C + (long)(row0 + 8) * ldc + off) = make_float2(v2, v3);
        }
    }
}

// ---------------------------------------------------------------------------
extern "C" void kernel_launch(void* const* d_in, const int* in_sizes, int n_in,
                              void* d_out, int out_size) {
    const float* storage = (const float*)d_in[0];
    const float* x       = (const float*)d_in[1];
    const float* ad_w1   = (const float*)d_in[2];
    const float* ad_b1   = (const float*)d_in[3];
    const float* ad_w2   = (const float*)d_in[4];
    const float* ad_b2   = (const float*)d_in[5];
    const float* imp_w1  = (const float*)d_in[6];
    const float* imp_b1  = (const float*)d_in[7];
    const float* imp_w2  = (const float*)d_in[8];
    const float* imp_b2  = (const float*)d_in[9];
    const float* w_in    = (const float*)d_in[10];
    const float* b_in    = (const float*)d_in[11];
    const float* w_out   = (const float*)d_in[12];
    const float* b_out   = (const float*)d_in[13];

    float* st  = (float*)d_out;                       // [B,K,D]
    float* agg = st + (long)BATCH * KS * DIM;         // [B,D]

    k1_stats<<<BATCH, 256>>>(storage, x, st);
    // ad-MLP hidden: relu(x @ ad_w1^T + ad_b1) -> g_had [B,128]
    gemm_tc<<<dim3(128, 2, 1), 256>>>(x, 0, 256, 0, ad_w1, 0, 256, 0,
                                      ad_b1, 0, nullptr, 2, 128, 0, 256, 1);
    k2_anom<<<BATCH / 8, 256>>>(ad_w2, ad_b2);
    // imp-MLP hidden: relu(ctx2 @ imp_w1^T + imp_b1) -> g_himp [B,256]
    gemm_tc<<<dim3(128, 4, 1), 256>>>(nullptr, 1, 512, 0, imp_w1, 0, 512, 0,
                                      imp_b1, 0, nullptr, 3, 256, 0, 512, 1);
    k4_imp<<<BATCH, 256>>>(imp_w2, imp_b2, x, st);
    // q = x @ wq^T + bq -> g_q [B,256]
    gemm_tc<<<dim3(128, 4, 1), 256>>>(x, 0, 256, 0, w_in, 0, 256, 0,
                                      b_in, 0, nullptr, 4, 256, 0, 256, 0);
    // qk[b,h,:] = Wk_h^T q_h -> g_qk [B,4,256]
    gemm_tc<<<dim3(128, 4, 4), 256>>>(nullptr, 4, 256, 64,
                                      w_in + 256 * 256, 1, 256, 64L * 256,
                                      nullptr, 0, nullptr, 5, 1024, 256, 64, 0);
    k7_attn<<<BATCH, 256>>>(st);
    // ctx[b, h*64+n] = wv_h[n,:] . s[b,h,:] + bv -> g_ctx [B,256]
    gemm_tc<<<dim3(128, 1, 4), 256>>>(nullptr, 6, 1024, 256,
                                      w_in + 512 * 256, 0, 256, 64L * 256,
                                      b_in + 512, 64, nullptr, 7, 256, 64, 256, 0);
    // agg = ctx @ attn_out_w^T + attn_out_b -> d_out tail
    gemm_tc<<<dim3(128, 4, 1), 256>>>(nullptr, 7, 256, 0, w_out, 0, 256, 0,
                                      b_out, 0, agg, 0, 256, 0, 256, 0);
    (void)in_sizes; (void)n_in; (void)out_size;
}